// round 2
// baseline (speedup 1.0000x reference)
#include <cuda_runtime.h>
#include <cstdint>

#define N_NODES 10000
#define N_EDGES 320000
#define IN_CH   256
#define OUT_CH  256
#define WPAD    320   // padded u32 words per bitmap row (need ceil(10000/32)=313)

// Scratch (device globals; no allocation allowed in kernel_launch)
__device__ unsigned g_bitmap[N_NODES * WPAD];          // 12.8 MB adjacency bitmap (row=src, bit=dst)
__device__ float    g_dinv[N_NODES];                   // D^{-1/2}
__device__ __align__(16) float g_xw[N_NODES * OUT_CH]; // dinv[j] * (X @ W)[j]

// ---------------------------------------------------------------------------
// 1) zero bitmap + set diagonal (self loops)
// ---------------------------------------------------------------------------
__global__ void k_init_bitmap() {
    int row = blockIdx.x;         // 10000 blocks
    int t   = threadIdx.x;        // 320 threads
    unsigned v = 0u;
    if (t == (row >> 5)) v = 1u << (row & 31);
    g_bitmap[row * WPAD + t] = v;
}

// ---------------------------------------------------------------------------
// 2) scatter edges: bitmap[src][dst] |= 1  (atomicOr dedupes duplicates)
//    edge_index is int32 (JAX x64 disabled downcasts int64 -> int32).
// ---------------------------------------------------------------------------
__global__ void k_scatter(const int* __restrict__ ei) {
    int e = blockIdx.x * blockDim.x + threadIdx.x;
    if (e >= N_EDGES) return;
    int src = ei[e];
    int dst = ei[N_EDGES + e];
    if ((unsigned)src >= N_NODES || (unsigned)dst >= N_NODES) return; // defensive
    atomicOr(&g_bitmap[src * WPAD + (dst >> 5)], 1u << (dst & 31));
}

// ---------------------------------------------------------------------------
// 3) degree via row popcount -> dinv = rsqrt(deg). One warp per row.
// ---------------------------------------------------------------------------
__global__ void k_degree() {
    int warp = (blockIdx.x * blockDim.x + threadIdx.x) >> 5;
    int lane = threadIdx.x & 31;
    if (warp >= N_NODES) return;
    const unsigned* rowp = g_bitmap + warp * WPAD;
    int s = 0;
    for (int w = lane; w < WPAD; w += 32) s += __popc(rowp[w]);
    #pragma unroll
    for (int o = 16; o; o >>= 1) s += __shfl_down_sync(0xffffffffu, s, o);
    if (lane == 0) g_dinv[warp] = rsqrtf((float)s);
}

// ---------------------------------------------------------------------------
// 4) SGEMM: g_xw[r][c] = dinv[r] * sum_k x[r][k] * w[k][c]
//    BM=128, BN=64, BK=16, 256 threads, 8x4 microtile per thread
// ---------------------------------------------------------------------------
#define BM 128
#define BN 64
#define BK 16

__global__ void k_gemm(const float* __restrict__ x, const float* __restrict__ w) {
    __shared__ float As[BK][BM + 4];   // padded to dodge store conflicts
    __shared__ float Bs[BK][BN];

    int tid = threadIdx.x;
    int tx  = tid & 15;    // 0..15 -> 4 cols each
    int ty  = tid >> 4;    // 0..15 -> 8 rows each
    int rowBase = blockIdx.y * BM;
    int colBase = blockIdx.x * BN;

    float acc[8][4];
    #pragma unroll
    for (int i = 0; i < 8; i++)
        #pragma unroll
        for (int j = 0; j < 4; j++) acc[i][j] = 0.0f;

    for (int k0 = 0; k0 < IN_CH; k0 += BK) {
        // --- global loads into registers ---
        float4 aReg[2];
        #pragma unroll
        for (int r = 0; r < 2; r++) {
            int idx = tid + 256 * r;
            int m   = idx >> 2;        // 0..127
            int kq  = idx & 3;         // k quad
            int grow = rowBase + m;
            if (grow < N_NODES)
                aReg[r] = *reinterpret_cast<const float4*>(&x[grow * IN_CH + k0 + kq * 4]);
            else
                aReg[r] = make_float4(0.f, 0.f, 0.f, 0.f);
        }
        int kk = tid >> 4;                 // 0..15
        int cc = (tid & 15) * 4;           // 0..60
        float4 bReg = *reinterpret_cast<const float4*>(&w[(k0 + kk) * OUT_CH + colBase + cc]);

        __syncthreads();   // previous tile compute done

        // --- store to smem (A transposed) ---
        #pragma unroll
        for (int r = 0; r < 2; r++) {
            int idx = tid + 256 * r;
            int m   = idx >> 2;
            int kq  = (idx & 3) * 4;
            As[kq + 0][m] = aReg[r].x;
            As[kq + 1][m] = aReg[r].y;
            As[kq + 2][m] = aReg[r].z;
            As[kq + 3][m] = aReg[r].w;
        }
        *reinterpret_cast<float4*>(&Bs[kk][cc]) = bReg;

        __syncthreads();

        // --- compute ---
        #pragma unroll
        for (int k = 0; k < BK; k++) {
            float4 a0 = *reinterpret_cast<const float4*>(&As[k][ty * 8]);
            float4 a1 = *reinterpret_cast<const float4*>(&As[k][ty * 8 + 4]);
            float4 b  = *reinterpret_cast<const float4*>(&Bs[k][tx * 4]);
            float av[8] = {a0.x, a0.y, a0.z, a0.w, a1.x, a1.y, a1.z, a1.w};
            float bv[4] = {b.x, b.y, b.z, b.w};
            #pragma unroll
            for (int i = 0; i < 8; i++)
                #pragma unroll
                for (int j = 0; j < 4; j++)
                    acc[i][j] += av[i] * bv[j];
        }
    }

    // --- epilogue: scale by dinv[row], store float4 ---
    #pragma unroll
    for (int i = 0; i < 8; i++) {
        int r = rowBase + ty * 8 + i;
        if (r < N_NODES) {
            float d = g_dinv[r];
            float4 o = make_float4(d * acc[i][0], d * acc[i][1],
                                   d * acc[i][2], d * acc[i][3]);
            *reinterpret_cast<float4*>(&g_xw[r * OUT_CH + colBase + tx * 4]) = o;
        }
    }
}

// ---------------------------------------------------------------------------
// 5) aggregate: out[i][:] = dinv[i] * sum_{j in row i bitmap} g_xw[j][:]
//    One block (256 threads) per row; deterministic compacted neighbor list.
// ---------------------------------------------------------------------------
__global__ void k_aggregate(float* __restrict__ out) {
    __shared__ int slist[2048];
    __shared__ int swarp[8];

    int row = blockIdx.x;
    int tid = threadIdx.x;       // 256, one output channel per thread
    int lane = tid & 31, wid = tid >> 5;

    const unsigned* rowp = g_bitmap + row * WPAD;
    unsigned w0 = rowp[tid];
    unsigned w1 = (tid + 256 < WPAD) ? rowp[tid + 256] : 0u;
    int c = __popc(w0) + __popc(w1);

    // warp inclusive scan of counts
    int inc = c;
    #pragma unroll
    for (int o = 1; o < 32; o <<= 1) {
        int v = __shfl_up_sync(0xffffffffu, inc, o);
        if (lane >= o) inc += v;
    }
    if (lane == 31) swarp[wid] = inc;
    __syncthreads();
    if (wid == 0) {
        int v = (lane < 8) ? swarp[lane] : 0;
        #pragma unroll
        for (int o = 1; o < 8; o <<= 1) {
            int t = __shfl_up_sync(0xffffffffu, v, o);
            if (lane >= o) v += t;
        }
        if (lane < 8) swarp[lane] = v;   // inclusive warp totals
    }
    __syncthreads();

    int off = (inc - c) + (wid ? swarp[wid - 1] : 0);
    int cnt = swarp[7];
    if (cnt > 2048) cnt = 2048;          // structural guard (never hit with random data)

    // deterministic compaction: thread's word tid, then word tid+256
    unsigned w = w0; int base = tid << 5;
    while (w) { int b = __ffs(w) - 1; w &= w - 1; if (off < 2048) slist[off++] = base + b; }
    w = w1; base = (tid + 256) << 5;
    while (w) { int b = __ffs(w) - 1; w &= w - 1; if (off < 2048) slist[off++] = base + b; }
    __syncthreads();

    // gather rows of g_xw (L2-resident), 4-way unroll for MLP
    float a0 = 0.f, a1 = 0.f, a2 = 0.f, a3 = 0.f;
    int n = 0;
    for (; n + 4 <= cnt; n += 4) {
        int j0 = slist[n], j1 = slist[n + 1], j2 = slist[n + 2], j3 = slist[n + 3];
        a0 += g_xw[j0 * OUT_CH + tid];
        a1 += g_xw[j1 * OUT_CH + tid];
        a2 += g_xw[j2 * OUT_CH + tid];
        a3 += g_xw[j3 * OUT_CH + tid];
    }
    for (; n < cnt; n++) a0 += g_xw[slist[n] * OUT_CH + tid];

    out[row * OUT_CH + tid] = g_dinv[row] * ((a0 + a1) + (a2 + a3));
}

// ---------------------------------------------------------------------------
extern "C" void kernel_launch(void* const* d_in, const int* in_sizes, int n_in,
                              void* d_out, int out_size) {
    const float* x  = (const float*)d_in[0];       // [10000, 256] f32
    const float* w  = (const float*)d_in[1];       // [256, 256]   f32
    const int*   ei = (const int*)d_in[2];         // [2, 320000]  i32 (JAX x64 off)
    float* out = (float*)d_out;                    // [10000, 256] f32

    k_init_bitmap<<<N_NODES, WPAD>>>();
    k_scatter<<<(N_EDGES + 255) / 256, 256>>>(ei);
    k_degree<<<(N_NODES * 32 + 255) / 256, 256>>>();
    dim3 ggrid(OUT_CH / BN, (N_NODES + BM - 1) / BM);
    k_gemm<<<ggrid, 256>>>(x, w);
    k_aggregate<<<N_NODES, 256>>>(out);
}